// round 13
// baseline (speedup 1.0000x reference)
#include <cuda_runtime.h>
#include <cuda_bf16.h>
#include <cstdint>

// ============================================================================
// GATv2 x2 + BN + skip + linear head.
// R13: (a) GEMM rebuilt as 4-warp CTA with 32x64 warp tile (-25% LDSM traffic
//      per MMA, B frags loaded per 16-col group to bound liveness),
//      (b) CSR: init_deg folded into scan1 (self-loop add + deg re-zero for
//      graph replay, count stashed in g_cur), scan3+selfloop merged,
//      (c) launch order arranged so ncu's 6th-launch window hits gemm1.
// conv1/conv2: R9 forms (2-edge pipelined; deeper unrolls regress via
// cross-CTA L1tex-queue spread). GEMMs: HMMA bf16 2-term split
// (tcgen05 rejected by the compute_103 PTX stage).
// ============================================================================

#define NEG_SLOPE 0.2f

static constexpr int NMAX  = 50000;
static constexpr int EMAX  = 800000;
static constexpr int EPMAX = EMAX + NMAX;

static constexpr int K1 = 160;
static constexpr int K2 = 256;

// ---- scratch ---------------------------------------------------------------
__device__ float          g_xlr1[(size_t)NMAX * 576]; // xl1|xr1|skip (fp32)
__device__ float          g_xlr2[(size_t)NMAX * 128]; // xl2|xr2      (fp32)
__device__ __nv_bfloat16  g_hhi [(size_t)NMAX * K2];
__device__ __nv_bfloat16  g_hlo [(size_t)NMAX * K2];
__device__ int   g_deg [NMAX];       // zero at entry; re-zeroed by scan1
__device__ int   g_off [NMAX + 1];
__device__ int   g_cur [NMAX];
__device__ int   g_esrc[EPMAX];
__device__ int   g_bsum[64];
__device__ __nv_bfloat16 g_W1thi[576 * K1];
__device__ __nv_bfloat16 g_W1tlo[576 * K1];
__device__ __nv_bfloat16 g_W2thi[128 * K2];
__device__ __nv_bfloat16 g_W2tlo[128 * K2];
__device__ float g_b1c [576];
__device__ float g_b2c [128];
__device__ float g_c1a [256];
__device__ float g_c1b [256];
__device__ float g_c2a [64];
__device__ float g_c2b [64];

// ---- helpers ----------------------------------------------------------------
__device__ __forceinline__ uint32_t smem_u32(const void* p) {
    uint32_t a;
    asm("{ .reg .u64 t; cvta.to.shared.u64 t, %1; cvt.u32.u64 %0, t; }"
        : "=r"(a) : "l"(p));
    return a;
}
__device__ __forceinline__ void ldsm_x4(uint32_t& r0, uint32_t& r1,
                                        uint32_t& r2, uint32_t& r3, uint32_t a) {
    asm volatile("ldmatrix.sync.aligned.m8n8.x4.shared.b16 {%0,%1,%2,%3}, [%4];"
                 : "=r"(r0), "=r"(r1), "=r"(r2), "=r"(r3) : "r"(a));
}
__device__ __forceinline__ void mma_bf16(float* c, const uint32_t* a,
                                         uint32_t b0, uint32_t b1) {
    asm volatile(
        "mma.sync.aligned.m16n8k16.row.col.f32.bf16.bf16.f32 "
        "{%0,%1,%2,%3}, {%4,%5,%6,%7}, {%8,%9}, {%0,%1,%2,%3};"
        : "+f"(c[0]), "+f"(c[1]), "+f"(c[2]), "+f"(c[3])
        : "r"(a[0]), "r"(a[1]), "r"(a[2]), "r"(a[3]), "r"(b0), "r"(b1));
}
__device__ __forceinline__ void bf16_split(float v, __nv_bfloat16& hi, __nv_bfloat16& lo) {
    hi = __float2bfloat16(v);
    lo = __float2bfloat16(v - __bfloat162float(hi));
}
__device__ __forceinline__ float lrelu(float t) {
    return fmaxf(t, 0.f) + NEG_SLOPE * fminf(t, 0.f);
}

// ---- 1a. prep layer 1 --------------------------------------------------------
__global__ void prep1_kernel(
    const float* __restrict__ Wl1, const float* __restrict__ bl1,
    const float* __restrict__ Wr1, const float* __restrict__ br1,
    const float* __restrict__ Ws,  const float* __restrict__ bs,
    const float* __restrict__ bias1, const float* __restrict__ g1,
    const float* __restrict__ b1,  const float* __restrict__ m1,
    const float* __restrict__ v1)
{
    int i = blockIdx.x * blockDim.x + threadIdx.x;
    if (i < 92160) {
        int nidx = i / K1, k = i % K1;
        float v;
        if (nidx < 256)      v = Wl1[k * 256 + nidx];
        else if (nidx < 512) v = Wr1[k * 256 + (nidx - 256)];
        else                 v = Ws [k * 64  + (nidx - 512)];
        __nv_bfloat16 hi, lo; bf16_split(v, hi, lo);
        g_W1thi[i] = hi; g_W1tlo[i] = lo;
    } else if (i < 92736) {
        int m = i - 92160;
        g_b1c[m] = (m < 256) ? bl1[m] : ((m < 512) ? br1[m - 256] : bs[m - 512]);
    } else if (i < 92992) {
        int j = i - 92736;
        float sc = g1[j] * rsqrtf(v1[j] + 1e-5f);
        g_c1a[j] = sc;
        g_c1b[j] = (bias1[j] - m1[j]) * sc + b1[j];
    }
}

// ---- 1b. prep layer 2 — side stream -------------------------------------------
__global__ void prep2_kernel(
    const float* __restrict__ Wl2, const float* __restrict__ bl2,
    const float* __restrict__ Wr2, const float* __restrict__ br2,
    const float* __restrict__ bias2, const float* __restrict__ g2,
    const float* __restrict__ b2,  const float* __restrict__ m2,
    const float* __restrict__ v2)
{
    int i = blockIdx.x * blockDim.x + threadIdx.x;
    if (i < 32768) {
        int nidx = i / K2, k = i % K2;
        float v = (nidx < 64) ? Wl2[k * 64 + nidx] : Wr2[k * 64 + (nidx - 64)];
        __nv_bfloat16 hi, lo; bf16_split(v, hi, lo);
        g_W2thi[i] = hi; g_W2tlo[i] = lo;
    } else if (i < 32896) {
        int m = i - 32768;
        g_b2c[m] = (m < 64) ? bl2[m] : br2[m - 64];
    } else if (i < 32960) {
        int j = i - 32896;
        float sc = g2[j] * rsqrtf(v2[j] + 1e-5f);
        g_c2a[j] = sc;
        g_c2b[j] = (bias2[j] - m2[j]) * sc + b2[j];
    }
}

// ---- 2. CSR build -------------------------------------------------------------
// g_deg is zero at entry (zero-init on first run, re-zeroed by scan1 each run).
__global__ void count_kernel(const int* __restrict__ ei, int e, int n) {
    int i = (blockIdx.x * blockDim.x + threadIdx.x) * 4;
    if (i + 3 < e) {
        int4 d = *(const int4*)(ei + e + i);
        if ((unsigned)d.x < (unsigned)n) atomicAdd(&g_deg[d.x], 1);
        if ((unsigned)d.y < (unsigned)n) atomicAdd(&g_deg[d.y], 1);
        if ((unsigned)d.z < (unsigned)n) atomicAdd(&g_deg[d.z], 1);
        if ((unsigned)d.w < (unsigned)n) atomicAdd(&g_deg[d.w], 1);
    } else {
        for (int j = i; j < e; ++j) {
            int d = ei[e + j];
            if ((unsigned)d < (unsigned)n) atomicAdd(&g_deg[d], 1);
        }
    }
}
// scan1: count+selfloop inclusive scan; stashes per-node count in g_cur;
// re-zeroes g_deg for the next graph replay.
__global__ void scan1_kernel(int n) {
    __shared__ int sh[1024];
    int tid = threadIdx.x;
    int i = blockIdx.x * 1024 + tid;
    int v = 0;
    if (i < n) {
        v = g_deg[i] + 1;     // +1 self-loop
        g_deg[i] = 0;         // reset for next replay
        g_cur[i] = v;         // stash count for scan3sl
    }
    sh[tid] = v;
    __syncthreads();
#pragma unroll
    for (int off = 1; off < 1024; off <<= 1) {
        int t = (tid >= off) ? sh[tid - off] : 0;
        __syncthreads();
        sh[tid] += t;
        __syncthreads();
    }
    if (i < n) g_off[i + 1] = sh[tid];
    if (tid == 1023) g_bsum[blockIdx.x] = sh[1023];
}
__global__ void scan2_kernel(int nblk) {
    __shared__ int sh[64];
    int tid = threadIdx.x;
    int v = (tid < nblk) ? g_bsum[tid] : 0;
    sh[tid] = v;
    __syncthreads();
#pragma unroll
    for (int off = 1; off < 64; off <<= 1) {
        int t = (tid >= off) ? sh[tid - off] : 0;
        __syncthreads();
        sh[tid] += t;
        __syncthreads();
    }
    if (tid < nblk) g_bsum[tid] = sh[tid] - v;
}
// scan3 + selfloop placement merged: finalize offsets, place self-loop, set cursor.
__global__ void scan3sl_kernel(int n) {
    int tid = threadIdx.x;
    int i = blockIdx.x * 1024 + tid;
    if (blockIdx.x == 0 && tid == 0) g_off[0] = 0;
    if (i < n) {
        int add = (blockIdx.x > 0) ? g_bsum[blockIdx.x] : 0;
        int fin = g_off[i + 1] + add;
        g_off[i + 1] = fin;
        int o = fin - g_cur[i];   // exclusive offset of node i
        g_esrc[o] = i;            // self-loop first
        g_cur[i] = o + 1;
    }
}
__global__ void scatter_kernel(const int* __restrict__ ei, int e, int n) {
    int i = (blockIdx.x * blockDim.x + threadIdx.x) * 4;
    if (i + 3 < e) {
        int4 s = *(const int4*)(ei + i);
        int4 d = *(const int4*)(ei + e + i);
        if ((unsigned)s.x < (unsigned)n && (unsigned)d.x < (unsigned)n)
            g_esrc[atomicAdd(&g_cur[d.x], 1)] = s.x;
        if ((unsigned)s.y < (unsigned)n && (unsigned)d.y < (unsigned)n)
            g_esrc[atomicAdd(&g_cur[d.y], 1)] = s.y;
        if ((unsigned)s.z < (unsigned)n && (unsigned)d.z < (unsigned)n)
            g_esrc[atomicAdd(&g_cur[d.z], 1)] = s.z;
        if ((unsigned)s.w < (unsigned)n && (unsigned)d.w < (unsigned)n)
            g_esrc[atomicAdd(&g_cur[d.w], 1)] = s.w;
    } else {
        for (int j = i; j < e; ++j) {
            int s = ei[j], d = ei[e + j];
            if ((unsigned)s < (unsigned)n && (unsigned)d < (unsigned)n)
                g_esrc[atomicAdd(&g_cur[d], 1)] = s;
        }
    }
}

// ---- 3/5. HMMA bf16-split GEMM: 4 warps, warp tile 32x64 ----------------------
// CTA 128x64; each warp owns rows [wid*32, wid*32+32) x all 64 cols.
// Per k16: A = 4 ldsm.x4 (2 mi x hi/lo), B = 8 ldsm.x4 loaded per 16-col group.
// MODE 0: A = fp32 x (split on the fly), K=160, Mo=576
// MODE 1: A = g_hhi/g_hlo,               K=256, Mo=128
template <int MODE>
__global__ __launch_bounds__(128) void gemm_mma_kernel(
    const float* __restrict__ X, int N)
{
    constexpr int K  = (MODE == 0) ? K1 : K2;
    constexpr int Mo = (MODE == 0) ? 576 : 128;
    constexpr int ST = 40;

    const __nv_bfloat16* __restrict__ Bhi = (MODE == 0) ? g_W1thi : g_W2thi;
    const __nv_bfloat16* __restrict__ Blo = (MODE == 0) ? g_W1tlo : g_W2tlo;
    const float* __restrict__ bias = (MODE == 0) ? g_b1c : g_b2c;
    float* __restrict__ C          = (MODE == 0) ? g_xlr1 : g_xlr2;

    __shared__ __nv_bfloat16 Ah_s[128][ST];
    __shared__ __nv_bfloat16 Al_s[128][ST];
    __shared__ __nv_bfloat16 Bh_s[64][ST];
    __shared__ __nv_bfloat16 Bl_s[64][ST];

    int tid  = threadIdx.x;
    int wid  = tid >> 5, lane = tid & 31;
    int rowBase = blockIdx.y * 128, colBase = blockIdx.x * 64;

    float acc[2][8][4];
#pragma unroll
    for (int i = 0; i < 2; i++)
#pragma unroll
        for (int j = 0; j < 8; j++)
#pragma unroll
            for (int q = 0; q < 4; q++) acc[i][j][q] = 0.f;

    int sel = lane >> 3;
    int a_row = wid * 32 + (lane & 7) + (sel & 1) * 8;
    int a_col = (sel >> 1) * 8;
    int b_row = (lane & 7) + (sel >> 1) * 8;   // + g*16
    int b_col = (sel & 1) * 8;

    for (int k0 = 0; k0 < K; k0 += 32) {
        __syncthreads();
        // ---- A fill: one row per thread, two 16-elem halves ----
        {
            int grow = rowBase + tid;
#pragma unroll
            for (int half = 0; half < 2; ++half) {
                if (MODE == 0) {
                    float vals[16];
                    if (grow < N) {
                        const float* px = X + (size_t)grow * K + k0 + half * 16;
#pragma unroll
                        for (int q = 0; q < 4; ++q)
                            *(float4*)&vals[q * 4] = *(const float4*)(px + q * 4);
                    } else {
#pragma unroll
                        for (int q = 0; q < 16; ++q) vals[q] = 0.f;
                    }
                    __nv_bfloat162 H[8], L[8];
#pragma unroll
                    for (int q = 0; q < 8; ++q) {
                        __nv_bfloat16 h0, l0, h1, l1;
                        bf16_split(vals[2*q],   h0, l0);
                        bf16_split(vals[2*q+1], h1, l1);
                        H[q] = __nv_bfloat162(h0, h1);
                        L[q] = __nv_bfloat162(l0, l1);
                    }
                    *(uint4*)&Ah_s[tid][half * 16]     = ((const uint4*)H)[0];
                    *(uint4*)&Ah_s[tid][half * 16 + 8] = ((const uint4*)H)[1];
                    *(uint4*)&Al_s[tid][half * 16]     = ((const uint4*)L)[0];
                    *(uint4*)&Al_s[tid][half * 16 + 8] = ((const uint4*)L)[1];
                } else {
                    uint4 h0 = make_uint4(0,0,0,0), h1 = h0, l0 = h0, l1 = h0;
                    if (grow < N) {
                        const __nv_bfloat16* ph = g_hhi + (size_t)grow * K + k0 + half * 16;
                        const __nv_bfloat16* pl = g_hlo + (size_t)grow * K + k0 + half * 16;
                        h0 = *(const uint4*)ph; h1 = *(const uint4*)(ph + 8);
                        l0 = *(const uint4*)pl; l1 = *(const uint4*)(pl + 8);
                    }
                    // h1/l1 contain elems [8..16) of this half (uint4 = 8 bf16)
                    *(uint4*)&Ah_s[tid][half * 16]     = h0;
                    *(uint4*)&Ah_s[tid][half * 16 + 8] = h1;
                    *(uint4*)&Al_s[tid][half * 16]     = l0;
                    *(uint4*)&Al_s[tid][half * 16 + 8] = l1;
                }
            }
        }
        // ---- B fill: r = tid>>1, half = tid&1 ----
        {
            int r = tid >> 1, half = tid & 1;
            int grow = colBase + r;
            const __nv_bfloat16* ph = Bhi + (size_t)grow * K + k0 + half * 16;
            const __nv_bfloat16* pl = Blo + (size_t)grow * K + k0 + half * 16;
            *(uint4*)&Bh_s[r][half * 16]     = *(const uint4*)ph;
            *(uint4*)&Bh_s[r][half * 16 + 8] = *(const uint4*)(ph + 8);
            *(uint4*)&Bl_s[r][half * 16]     = *(const uint4*)pl;
            *(uint4*)&Bl_s[r][half * 16 + 8] = *(const uint4*)(pl + 8);
        }
        __syncthreads();

#pragma unroll
        for (int kk = 0; kk < 32; kk += 16) {
            uint32_t ah[2][4], al[2][4];
#pragma unroll
            for (int mi = 0; mi < 2; ++mi) {
                uint32_t addr_h = smem_u32(&Ah_s[a_row + mi * 16][a_col + kk]);
                uint32_t addr_l = smem_u32(&Al_s[a_row + mi * 16][a_col + kk]);
                ldsm_x4(ah[mi][0], ah[mi][1], ah[mi][2], ah[mi][3], addr_h);
                ldsm_x4(al[mi][0], al[mi][1], al[mi][2], al[mi][3], addr_l);
            }
#pragma unroll
            for (int g = 0; g < 4; ++g) {
                uint32_t bh0, bh1, bh2, bh3, bl0, bl1, bl2, bl3;
                uint32_t addr_h = smem_u32(&Bh_s[g * 16 + b_row][b_col + kk]);
                uint32_t addr_l = smem_u32(&Bl_s[g * 16 + b_row][b_col + kk]);
                ldsm_x4(bh0, bh1, bh2, bh3, addr_h);
                ldsm_x4(bl0, bl1, bl2, bl3, addr_l);
#pragma unroll
                for (int mi = 0; mi < 2; ++mi) {
                    mma_bf16(acc[mi][g*2],     ah[mi], bh0, bh1);
                    mma_bf16(acc[mi][g*2],     ah[mi], bl0, bl1);
                    mma_bf16(acc[mi][g*2],     al[mi], bh0, bh1);
                    mma_bf16(acc[mi][g*2 + 1], ah[mi], bh2, bh3);
                    mma_bf16(acc[mi][g*2 + 1], ah[mi], bl2, bl3);
                    mma_bf16(acc[mi][g*2 + 1], al[mi], bh2, bh3);
                }
            }
        }
    }

    int fr = lane >> 2, fc = (lane & 3) * 2;
#pragma unroll
    for (int mi = 0; mi < 2; ++mi) {
#pragma unroll
        for (int nj = 0; nj < 8; ++nj) {
            int gcol = colBase + nj * 8 + fc;
            float bx = bias[gcol], by = bias[gcol + 1];
            int r0 = rowBase + wid * 32 + mi * 16 + fr;
            if (r0 < N) {
                float2 o = make_float2(acc[mi][nj][0] + bx, acc[mi][nj][1] + by);
                *(float2*)(C + (size_t)r0 * Mo + gcol) = o;
            }
            if (r0 + 8 < N) {
                float2 o = make_float2(acc[mi][nj][2] + bx, acc[mi][nj][3] + by);
                *(float2*)(C + (size_t)(r0 + 8) * Mo + gcol) = o;
            }
        }
    }
}

// ---- 4. conv1 aggregation: one warp per dst, 2-edge pipelined (R9) -----------
__global__ __launch_bounds__(256) void conv1_agg_kernel(
    const float* __restrict__ att1, int n)
{
    int gw = (blockIdx.x * blockDim.x + threadIdx.x) >> 5;
    int lane = threadIdx.x & 31;
    if (gw >= n) return;

    const float* xr_p = g_xlr1 + (size_t)gw * 576 + 256 + lane * 8;
    float4 xr0 = *(const float4*)xr_p;
    float4 xr1 = *(const float4*)(xr_p + 4);
    float4 at0 = *(const float4*)(att1 + lane * 8);
    float4 at1 = *(const float4*)(att1 + lane * 8 + 4);

    float den = 0.f;
    float acc[8];
#pragma unroll
    for (int j = 0; j < 8; j++) acc[j] = 0.f;

    int e0 = g_off[gw], e1 = g_off[gw + 1];
    int e = e0;
    for (; e + 2 <= e1; e += 2) {
        int s0 = g_esrc[e], s1 = g_esrc[e + 1];
        const float* pa = g_xlr1 + (size_t)s0 * 576 + lane * 8;
        const float* pb = g_xlr1 + (size_t)s1 * 576 + lane * 8;
        float4 xa0 = *(const float4*)pa;
        float4 xa1 = *(const float4*)(pa + 4);
        float4 xb0 = *(const float4*)pb;
        float4 xb1 = *(const float4*)(pb + 4);

        float p0, p1;
        p0  = at0.x * lrelu(xa0.x + xr0.x);
        p1  = at0.x * lrelu(xb0.x + xr0.x);
        p0 += at0.y * lrelu(xa0.y + xr0.y);
        p1 += at0.y * lrelu(xb0.y + xr0.y);
        p0 += at0.z * lrelu(xa0.z + xr0.z);
        p1 += at0.z * lrelu(xb0.z + xr0.z);
        p0 += at0.w * lrelu(xa0.w + xr0.w);
        p1 += at0.w * lrelu(xb0.w + xr0.w);
        p0 += at1.x * lrelu(xa1.x + xr1.x);
        p1 += at1.x * lrelu(xb1.x + xr1.x);
        p0 += at1.y * lrelu(xa1.y + xr1.y);
        p1 += at1.y * lrelu(xb1.y + xr1.y);
        p0 += at1.z * lrelu(xa1.z + xr1.z);
        p1 += at1.z * lrelu(xb1.z + xr1.z);
        p0 += at1.w * lrelu(xa1.w + xr1.w);
        p1 += at1.w * lrelu(xb1.w + xr1.w);

        p0 += __shfl_xor_sync(0xffffffffu, p0, 1);
        p1 += __shfl_xor_sync(0xffffffffu, p1, 1);
        p0 += __shfl_xor_sync(0xffffffffu, p0, 2);
        p1 += __shfl_xor_sync(0xffffffffu, p1, 2);
        p0 += __shfl_xor_sync(0xffffffffu, p0, 4);
        p1 += __shfl_xor_sync(0xffffffffu, p1, 4);

        float w0 = __expf(fminf(p0, 80.f));
        float w1 = __expf(fminf(p1, 80.f));
        den += w0 + w1;
        acc[0] += w0 * xa0.x + w1 * xb0.x;
        acc[1] += w0 * xa0.y + w1 * xb0.y;
        acc[2] += w0 * xa0.z + w1 * xb0.z;
        acc[3] += w0 * xa0.w + w1 * xb0.w;
        acc[4] += w0 * xa1.x + w1 * xb1.x;
        acc[5] += w0 * xa1.y + w1 * xb1.y;
        acc[6] += w0 * xa1.z + w1 * xb1.z;
        acc[7] += w0 * xa1.w + w1 * xb1.w;
    }
    if (e < e1) {
        int s = g_esrc[e];
        const float* pa = g_xlr1 + (size_t)s * 576 + lane * 8;
        float4 x0 = *(const float4*)pa;
        float4 x1 = *(const float4*)(pa + 4);
        float p;
        p  = at0.x * lrelu(x0.x + xr0.x);
        p += at0.y * lrelu(x0.y + xr0.y);
        p += at0.z * lrelu(x0.z + xr0.z);
        p += at0.w * lrelu(x0.w + xr0.w);
        p += at1.x * lrelu(x1.x + xr1.x);
        p += at1.y * lrelu(x1.y + xr1.y);
        p += at1.z * lrelu(x1.z + xr1.z);
        p += at1.w * lrelu(x1.w + xr1.w);
        p += __shfl_xor_sync(0xffffffffu, p, 1);
        p += __shfl_xor_sync(0xffffffffu, p, 2);
        p += __shfl_xor_sync(0xffffffffu, p, 4);
        float w = __expf(fminf(p, 80.f));
        den += w;
        acc[0] += w * x0.x; acc[1] += w * x0.y;
        acc[2] += w * x0.z; acc[3] += w * x0.w;
        acc[4] += w * x1.x; acc[5] += w * x1.y;
        acc[6] += w * x1.z; acc[7] += w * x1.w;
    }

    float inv = 1.f / den;
    int c = lane * 8;
    __nv_bfloat162 ph[4], pl[4];
#pragma unroll
    for (int j = 0; j < 4; ++j) {
        float v0 = fmaxf(acc[2*j]   * inv * g_c1a[c + 2*j]   + g_c1b[c + 2*j],   0.f);
        float v1 = fmaxf(acc[2*j+1] * inv * g_c1a[c + 2*j+1] + g_c1b[c + 2*j+1], 0.f);
        __nv_bfloat16 h0, l0, h1, l1;
        bf16_split(v0, h0, l0);
        bf16_split(v1, h1, l1);
        ph[j] = __nv_bfloat162(h0, h1);
        pl[j] = __nv_bfloat162(l0, l1);
    }
    *(uint4*)(g_hhi + (size_t)gw * 256 + c) = *(const uint4*)ph;
    *(uint4*)(g_hlo + (size_t)gw * 256 + c) = *(const uint4*)pl;
}

// ---- 6. conv2 aggregation + BN2 + relu + skip + head (R9 form) ---------------
__global__ __launch_bounds__(256) void conv2_agg_kernel(
    const float* __restrict__ att2, const float* __restrict__ Wo,
    const float* __restrict__ bo, float* __restrict__ out, int n)
{
    int gw = (blockIdx.x * blockDim.x + threadIdx.x) >> 5;
    int lane = threadIdx.x & 31;
    if (gw >= n) return;

    float2 xr = *(const float2*)(g_xlr2 + (size_t)gw * 128 + 64 + lane * 2);
    float2 at = *(const float2*)(att2 + lane * 2);

    float den = 0.f, a0 = 0.f, a1 = 0.f;

    int e0 = g_off[gw], e1 = g_off[gw + 1];
    int e = e0;
    for (; e + 2 <= e1; e += 2) {
        int s0 = g_esrc[e], s1 = g_esrc[e + 1];
        float2 xa = *(const float2*)(g_xlr2 + (size_t)s0 * 128 + lane * 2);
        float2 xb = *(const float2*)(g_xlr2 + (size_t)s1 * 128 + lane * 2);
        float p0 = at.x * lrelu(xa.x + xr.x) + at.y * lrelu(xa.y + xr.y);
        float p1 = at.x * lrelu(xb.x + xr.x) + at.y * lrelu(xb.y + xr.y);
        p0 += __shfl_xor_sync(0xffffffffu, p0, 1);
        p1 += __shfl_xor_sync(0xffffffffu, p1, 1);
        p0 += __shfl_xor_sync(0xffffffffu, p0, 2);
        p1 += __shfl_xor_sync(0xffffffffu, p1, 2);
        p0 += __shfl_xor_sync(0xffffffffu, p0, 4);
        p1 += __shfl_xor_sync(0xffffffffu, p1, 4);
        p0 += __shfl_xor_sync(0xffffffffu, p0, 8);
        p1 += __shfl_xor_sync(0xffffffffu, p1, 8);
        p0 += __shfl_xor_sync(0xffffffffu, p0, 16);
        p1 += __shfl_xor_sync(0xffffffffu, p1, 16);
        float w0 = __expf(fminf(p0, 80.f));
        float w1 = __expf(fminf(p1, 80.f));
        den += w0 + w1;
        a0 += w0 * xa.x + w1 * xb.x;
        a1 += w0 * xa.y + w1 * xb.y;
    }
    if (e < e1) {
        int s = g_esrc[e];
        float2 x = *(const float2*)(g_xlr2 + (size_t)s * 128 + lane * 2);
        float p = at.x * lrelu(x.x + xr.x) + at.y * lrelu(x.y + xr.y);
        p += __shfl_xor_sync(0xffffffffu, p, 1);
        p += __shfl_xor_sync(0xffffffffu, p, 2);
        p += __shfl_xor_sync(0xffffffffu, p, 4);
        p += __shfl_xor_sync(0xffffffffu, p, 8);
        p += __shfl_xor_sync(0xffffffffu, p, 16);
        float w = __expf(fminf(p, 80.f));
        den += w;
        a0 += w * x.x;
        a1 += w * x.y;
    }

    float inv = 1.f / den;
    int c = lane * 2;
    float2 sk = *(const float2*)(g_xlr1 + (size_t)gw * 576 + 512 + c);
    float h0 = fmaxf(a0 * inv * g_c2a[c + 0] + g_c2b[c + 0], 0.f) + sk.x;
    float h1 = fmaxf(a1 * inv * g_c2a[c + 1] + g_c2b[c + 1], 0.f) + sk.y;

    float r = h0 * Wo[c] + h1 * Wo[c + 1];
    r += __shfl_xor_sync(0xffffffffu, r, 1);
    r += __shfl_xor_sync(0xffffffffu, r, 2);
    r += __shfl_xor_sync(0xffffffffu, r, 4);
    r += __shfl_xor_sync(0xffffffffu, r, 8);
    r += __shfl_xor_sync(0xffffffffu, r, 16);
    if (lane == 0) out[gw] = r + bo[0];
}

// ---- host --------------------------------------------------------------------
extern "C" void kernel_launch(void* const* d_in, const int* in_sizes, int n_in,
                              void* d_out, int out_size)
{
    const float* x     = (const float*)d_in[0];
    const int*   ei    = (const int*)d_in[1];
    const float* Wl1   = (const float*)d_in[2];
    const float* bl1   = (const float*)d_in[3];
    const float* Wr1   = (const float*)d_in[4];
    const float* br1   = (const float*)d_in[5];
    const float* att1  = (const float*)d_in[6];
    const float* bias1 = (const float*)d_in[7];
    const float* g1    = (const float*)d_in[8];
    const float* b1    = (const float*)d_in[9];
    const float* m1    = (const float*)d_in[10];
    const float* v1    = (const float*)d_in[11];
    const float* Wl2   = (const float*)d_in[12];
    const float* bl2   = (const float*)d_in[13];
    const float* Wr2   = (const float*)d_in[14];
    const float* br2   = (const float*)d_in[15];
    const float* att2  = (const float*)d_in[16];
    const float* bias2 = (const float*)d_in[17];
    const float* g2    = (const float*)d_in[18];
    const float* b2    = (const float*)d_in[19];
    const float* m2    = (const float*)d_in[20];
    const float* v2    = (const float*)d_in[21];
    const float* Ws    = (const float*)d_in[22];
    const float* bs    = (const float*)d_in[23];
    const float* Wo    = (const float*)d_in[24];
    const float* bo    = (const float*)d_in[25];

    int n = in_sizes[0] / 160;
    int e = in_sizes[1] / 2;
    int nblk = (n + 1023) / 1024;
    int e4 = (e + 3) / 4;

    static cudaStream_t s_side = nullptr;
    static cudaEvent_t ev_fork = nullptr, ev_join = nullptr;
    if (!s_side) {
        cudaStreamCreateWithFlags(&s_side, cudaStreamNonBlocking);
        cudaEventCreateWithFlags(&ev_fork, cudaEventDisableTiming);
        cudaEventCreateWithFlags(&ev_join, cudaEventDisableTiming);
    }

    cudaEventRecord(ev_fork, 0);
    cudaStreamWaitEvent(s_side, ev_fork, 0);

    // side (1-4): CSR front half
    count_kernel <<<(e4 + 255) / 256, 256, 0, s_side>>>(ei, e, n);   // #1
    scan1_kernel <<<nblk, 1024, 0, s_side>>>(n);                     // #2
    scan2_kernel <<<1, 64, 0, s_side>>>(nblk);                       // #3
    scan3sl_kernel<<<nblk, 1024, 0, s_side>>>(n);                    // #4

    // main (5-6): prep1 -> GEMM1   (launch #6 = gemm1 for ncu visibility)
    prep1_kernel<<<(92992 + 255) / 256, 256>>>(                      // #5
        Wl1, bl1, Wr1, br1, Ws, bs, bias1, g1, b1, m1, v1);
    {
        dim3 grid(576 / 64, (n + 127) / 128);
        gemm_mma_kernel<0><<<grid, 128>>>(x, n);                     // #6
    }

    // side (7-8): scatter + prep2
    scatter_kernel<<<(e4 + 255) / 256, 256, 0, s_side>>>(ei, e, n);  // #7
    prep2_kernel<<<(32960 + 255) / 256, 256, 0, s_side>>>(           // #8
        Wl2, bl2, Wr2, br2, bias2, g2, b2, m2, v2);
    cudaEventRecord(ev_join, s_side);

    cudaStreamWaitEvent(0, ev_join, 0);

    conv1_agg_kernel<<<(n + 7) / 8, 256>>>(att1, n);                 // #9
    {
        dim3 grid(128 / 64, (n + 127) / 128);
        gemm_mma_kernel<1><<<grid, 128>>>(nullptr, n);               // #10
    }
    conv2_agg_kernel<<<(n + 7) / 8, 256>>>(att2, Wo, bo, (float*)d_out, n); // #11
}

// round 14
// speedup vs baseline: 1.0922x; 1.0922x over previous
#include <cuda_runtime.h>
#include <cuda_bf16.h>
#include <cstdint>

// ============================================================================
// GATv2 x2 + BN + skip + linear head.
// R14: restore the measured-best R9 configuration (353.9us):
//   - GEMM: 8-warp CTA, 32x32 warp tile, NO register prefetch
//   - conv1: 2-edge pipelined warp/dst (4-edge regresses: L1tex-queue spread)
//   - conv2: full-warp 2-edge (8-lane-group variant was -3us slower)
//   - prep: single combined kernel on main stream
//   - CSR on side stream (merged kernels: scan1 folds init+selfloop count,
//     scan3sl merges offset-finalize + self-loop placement) — hidden under
//     prep+GEMM1, zero visible cost.
// GEMMs: HMMA bf16 2-term split (hi*hi+hi*lo+lo*hi, fp32 acc); tcgen05 is
// unavailable (harness compiles through compute_103 PTX which rejects it).
// ============================================================================

#define NEG_SLOPE 0.2f

static constexpr int NMAX  = 50000;
static constexpr int EMAX  = 800000;
static constexpr int EPMAX = EMAX + NMAX;

static constexpr int K1 = 160;
static constexpr int K2 = 256;

// ---- scratch ---------------------------------------------------------------
__device__ float          g_xlr1[(size_t)NMAX * 576]; // xl1|xr1|skip (fp32)
__device__ float          g_xlr2[(size_t)NMAX * 128]; // xl2|xr2      (fp32)
__device__ __nv_bfloat16  g_hhi [(size_t)NMAX * K2];
__device__ __nv_bfloat16  g_hlo [(size_t)NMAX * K2];
__device__ int   g_deg [NMAX];       // zero at entry; re-zeroed by scan1
__device__ int   g_off [NMAX + 1];
__device__ int   g_cur [NMAX];
__device__ int   g_esrc[EPMAX];
__device__ int   g_bsum[64];
__device__ __nv_bfloat16 g_W1thi[576 * K1];
__device__ __nv_bfloat16 g_W1tlo[576 * K1];
__device__ __nv_bfloat16 g_W2thi[128 * K2];
__device__ __nv_bfloat16 g_W2tlo[128 * K2];
__device__ float g_b1c [576];
__device__ float g_b2c [128];
__device__ float g_c1a [256];
__device__ float g_c1b [256];
__device__ float g_c2a [64];
__device__ float g_c2b [64];

// ---- helpers ----------------------------------------------------------------
__device__ __forceinline__ uint32_t smem_u32(const void* p) {
    uint32_t a;
    asm("{ .reg .u64 t; cvta.to.shared.u64 t, %1; cvt.u32.u64 %0, t; }"
        : "=r"(a) : "l"(p));
    return a;
}
__device__ __forceinline__ void ldsm_x4(uint32_t& r0, uint32_t& r1,
                                        uint32_t& r2, uint32_t& r3, uint32_t a) {
    asm volatile("ldmatrix.sync.aligned.m8n8.x4.shared.b16 {%0,%1,%2,%3}, [%4];"
                 : "=r"(r0), "=r"(r1), "=r"(r2), "=r"(r3) : "r"(a));
}
__device__ __forceinline__ void mma_bf16(float* c, uint32_t a0, uint32_t a1,
                                         uint32_t a2, uint32_t a3,
                                         uint32_t b0, uint32_t b1) {
    asm volatile(
        "mma.sync.aligned.m16n8k16.row.col.f32.bf16.bf16.f32 "
        "{%0,%1,%2,%3}, {%4,%5,%6,%7}, {%8,%9}, {%0,%1,%2,%3};"
        : "+f"(c[0]), "+f"(c[1]), "+f"(c[2]), "+f"(c[3])
        : "r"(a0), "r"(a1), "r"(a2), "r"(a3), "r"(b0), "r"(b1));
}
__device__ __forceinline__ void bf16_split(float v, __nv_bfloat16& hi, __nv_bfloat16& lo) {
    hi = __float2bfloat16(v);
    lo = __float2bfloat16(v - __bfloat162float(hi));
}
__device__ __forceinline__ float lrelu(float t) {
    return fmaxf(t, 0.f) + NEG_SLOPE * fminf(t, 0.f);
}

// ---- 1. prep (combined, main stream — R9 form) -------------------------------
__global__ void prep_kernel(
    const float* __restrict__ Wl1, const float* __restrict__ bl1,
    const float* __restrict__ Wr1, const float* __restrict__ br1,
    const float* __restrict__ Ws,  const float* __restrict__ bs,
    const float* __restrict__ Wl2, const float* __restrict__ bl2,
    const float* __restrict__ Wr2, const float* __restrict__ br2,
    const float* __restrict__ bias1, const float* __restrict__ g1,
    const float* __restrict__ b1,  const float* __restrict__ m1,
    const float* __restrict__ v1,
    const float* __restrict__ bias2, const float* __restrict__ g2,
    const float* __restrict__ b2,  const float* __restrict__ m2,
    const float* __restrict__ v2)
{
    int i = blockIdx.x * blockDim.x + threadIdx.x;
    if (i < 92160) {
        int nidx = i / K1, k = i % K1;
        float v;
        if (nidx < 256)      v = Wl1[k * 256 + nidx];
        else if (nidx < 512) v = Wr1[k * 256 + (nidx - 256)];
        else                 v = Ws [k * 64  + (nidx - 512)];
        __nv_bfloat16 hi, lo; bf16_split(v, hi, lo);
        g_W1thi[i] = hi; g_W1tlo[i] = lo;
    } else if (i < 92736) {
        int m = i - 92160;
        g_b1c[m] = (m < 256) ? bl1[m] : ((m < 512) ? br1[m - 256] : bs[m - 512]);
    } else if (i < 125504) {
        int j = i - 92736;
        int nidx = j / K2, k = j % K2;
        float v = (nidx < 64) ? Wl2[k * 64 + nidx] : Wr2[k * 64 + (nidx - 64)];
        __nv_bfloat16 hi, lo; bf16_split(v, hi, lo);
        g_W2thi[j] = hi; g_W2tlo[j] = lo;
    } else if (i < 125632) {
        int m = i - 125504;
        g_b2c[m] = (m < 64) ? bl2[m] : br2[m - 64];
    } else if (i < 125888) {
        int j = i - 125632;
        float sc = g1[j] * rsqrtf(v1[j] + 1e-5f);
        g_c1a[j] = sc;
        g_c1b[j] = (bias1[j] - m1[j]) * sc + b1[j];
    } else if (i < 125952) {
        int j = i - 125888;
        float sc = g2[j] * rsqrtf(v2[j] + 1e-5f);
        g_c2a[j] = sc;
        g_c2b[j] = (bias2[j] - m2[j]) * sc + b2[j];
    }
}

// ---- 2. CSR build (side stream; merged kernels) -------------------------------
__global__ void count_kernel(const int* __restrict__ ei, int e, int n) {
    int i = (blockIdx.x * blockDim.x + threadIdx.x) * 4;
    if (i + 3 < e) {
        int4 d = *(const int4*)(ei + e + i);
        if ((unsigned)d.x < (unsigned)n) atomicAdd(&g_deg[d.x], 1);
        if ((unsigned)d.y < (unsigned)n) atomicAdd(&g_deg[d.y], 1);
        if ((unsigned)d.z < (unsigned)n) atomicAdd(&g_deg[d.z], 1);
        if ((unsigned)d.w < (unsigned)n) atomicAdd(&g_deg[d.w], 1);
    } else {
        for (int j = i; j < e; ++j) {
            int d = ei[e + j];
            if ((unsigned)d < (unsigned)n) atomicAdd(&g_deg[d], 1);
        }
    }
}
// scan1: (count+1 selfloop) inclusive scan; stashes count in g_cur; re-zeroes deg.
__global__ void scan1_kernel(int n) {
    __shared__ int sh[1024];
    int tid = threadIdx.x;
    int i = blockIdx.x * 1024 + tid;
    int v = 0;
    if (i < n) {
        v = g_deg[i] + 1;
        g_deg[i] = 0;
        g_cur[i] = v;
    }
    sh[tid] = v;
    __syncthreads();
#pragma unroll
    for (int off = 1; off < 1024; off <<= 1) {
        int t = (tid >= off) ? sh[tid - off] : 0;
        __syncthreads();
        sh[tid] += t;
        __syncthreads();
    }
    if (i < n) g_off[i + 1] = sh[tid];
    if (tid == 1023) g_bsum[blockIdx.x] = sh[1023];
}
__global__ void scan2_kernel(int nblk) {
    __shared__ int sh[64];
    int tid = threadIdx.x;
    int v = (tid < nblk) ? g_bsum[tid] : 0;
    sh[tid] = v;
    __syncthreads();
#pragma unroll
    for (int off = 1; off < 64; off <<= 1) {
        int t = (tid >= off) ? sh[tid - off] : 0;
        __syncthreads();
        sh[tid] += t;
        __syncthreads();
    }
    if (tid < nblk) g_bsum[tid] = sh[tid] - v;
}
// finalize offsets + place self-loop + set scatter cursor.
__global__ void scan3sl_kernel(int n) {
    int tid = threadIdx.x;
    int i = blockIdx.x * 1024 + tid;
    if (blockIdx.x == 0 && tid == 0) g_off[0] = 0;
    if (i < n) {
        int add = (blockIdx.x > 0) ? g_bsum[blockIdx.x] : 0;
        int fin = g_off[i + 1] + add;
        g_off[i + 1] = fin;
        int o = fin - g_cur[i];
        g_esrc[o] = i;
        g_cur[i] = o + 1;
    }
}
__global__ void scatter_kernel(const int* __restrict__ ei, int e, int n) {
    int i = (blockIdx.x * blockDim.x + threadIdx.x) * 4;
    if (i + 3 < e) {
        int4 s = *(const int4*)(ei + i);
        int4 d = *(const int4*)(ei + e + i);
        if ((unsigned)s.x < (unsigned)n && (unsigned)d.x < (unsigned)n)
            g_esrc[atomicAdd(&g_cur[d.x], 1)] = s.x;
        if ((unsigned)s.y < (unsigned)n && (unsigned)d.y < (unsigned)n)
            g_esrc[atomicAdd(&g_cur[d.y], 1)] = s.y;
        if ((unsigned)s.z < (unsigned)n && (unsigned)d.z < (unsigned)n)
            g_esrc[atomicAdd(&g_cur[d.z], 1)] = s.z;
        if ((unsigned)s.w < (unsigned)n && (unsigned)d.w < (unsigned)n)
            g_esrc[atomicAdd(&g_cur[d.w], 1)] = s.w;
    } else {
        for (int j = i; j < e; ++j) {
            int s = ei[j], d = ei[e + j];
            if ((unsigned)s < (unsigned)n && (unsigned)d < (unsigned)n)
                g_esrc[atomicAdd(&g_cur[d], 1)] = s;
        }
    }
}

// ---- 3/5. HMMA bf16-split GEMM (R9 form: 8 warps, 32x32 warp tile) ------------
// MODE 0: A = fp32 x (split on the fly in fill), K=160, Mo=576
// MODE 1: A = g_hhi/g_hlo (pre-split),           K=256, Mo=128
template <int MODE>
__global__ __launch_bounds__(256) void gemm_mma_kernel(
    const float* __restrict__ X, int N)
{
    constexpr int K  = (MODE == 0) ? K1 : K2;
    constexpr int Mo = (MODE == 0) ? 576 : 128;
    constexpr int ST = 40;

    const __nv_bfloat16* __restrict__ Bhi = (MODE == 0) ? g_W1thi : g_W2thi;
    const __nv_bfloat16* __restrict__ Blo = (MODE == 0) ? g_W1tlo : g_W2tlo;
    const float* __restrict__ bias = (MODE == 0) ? g_b1c : g_b2c;
    float* __restrict__ C          = (MODE == 0) ? g_xlr1 : g_xlr2;

    __shared__ __nv_bfloat16 Ah_s[128][ST];
    __shared__ __nv_bfloat16 Al_s[128][ST];
    __shared__ __nv_bfloat16 Bh_s[64][ST];
    __shared__ __nv_bfloat16 Bl_s[64][ST];

    int tid  = threadIdx.x;
    int wid  = tid >> 5, lane = tid & 31;
    int wm   = wid & 3;
    int wn   = wid >> 2;
    int rowBase = blockIdx.y * 128, colBase = blockIdx.x * 64;

    float acc[2][4][4];
#pragma unroll
    for (int i = 0; i < 2; i++)
#pragma unroll
        for (int j = 0; j < 4; j++)
#pragma unroll
            for (int q = 0; q < 4; q++) acc[i][j][q] = 0.f;

    int sel = lane >> 3;
    int a_row = wm * 32 + (lane & 7) + (sel & 1) * 8;
    int a_col = (sel >> 1) * 8;
    int b_row = wn * 32 + (lane & 7) + (sel >> 1) * 8;
    int b_col = (sel & 1) * 8;

    for (int k0 = 0; k0 < K; k0 += 32) {
        __syncthreads();
        if (MODE == 0) {
            int r = tid >> 1, half = tid & 1;
            int grow = rowBase + r;
            float vals[16];
            if (grow < N) {
                const float* px = X + (size_t)grow * K + k0 + half * 16;
#pragma unroll
                for (int q = 0; q < 4; ++q)
                    *(float4*)&vals[q * 4] = *(const float4*)(px + q * 4);
            } else {
#pragma unroll
                for (int q = 0; q < 16; ++q) vals[q] = 0.f;
            }
            __nv_bfloat162 H[8], L[8];
#pragma unroll
            for (int q = 0; q < 8; ++q) {
                __nv_bfloat16 h0, l0, h1, l1;
                bf16_split(vals[2*q],   h0, l0);
                bf16_split(vals[2*q+1], h1, l1);
                H[q] = __nv_bfloat162(h0, h1);
                L[q] = __nv_bfloat162(l0, l1);
            }
            *(uint4*)&Ah_s[r][half * 16]     = ((const uint4*)H)[0];
            *(uint4*)&Ah_s[r][half * 16 + 8] = ((const uint4*)H)[1];
            *(uint4*)&Al_s[r][half * 16]     = ((const uint4*)L)[0];
            *(uint4*)&Al_s[r][half * 16 + 8] = ((const uint4*)L)[1];
        } else {
            int r = tid >> 1, half = tid & 1;
            int grow = rowBase + r;
            uint4 h0 = make_uint4(0,0,0,0), h1 = h0, l0 = h0, l1 = h0;
            if (grow < N) {
                const __nv_bfloat16* ph = g_hhi + (size_t)grow * K + k0 + half * 16;
                const __nv_bfloat16* pl = g_hlo + (size_t)grow * K + k0 + half * 16;
                h0 = *(const uint4*)ph;  h1 = *(const uint4*)(ph + 8);
                l0 = *(const uint4*)pl;  l1 = *(const uint4*)(pl + 8);
            }
            *(uint4*)&Ah_s[r][half * 16]     = h0;
            *(uint4*)&Ah_s[r][half * 16 + 8] = h1;
            *(uint4*)&Al_s[r][half * 16]     = l0;
            *(uint4*)&Al_s[r][half * 16 + 8] = l1;
        }
        {
            int r = tid >> 2, q = tid & 3;
            int grow = colBase + r;
            const __nv_bfloat16* ph = Bhi + (size_t)grow * K + k0 + q * 8;
            const __nv_bfloat16* pl = Blo + (size_t)grow * K + k0 + q * 8;
            *(uint4*)&Bh_s[r][q * 8] = *(const uint4*)ph;
            *(uint4*)&Bl_s[r][q * 8] = *(const uint4*)pl;
        }
        __syncthreads();

#pragma unroll
        for (int kk = 0; kk < 32; kk += 16) {
            uint32_t ah[2][4], al[2][4];
#pragma unroll
            for (int mi = 0; mi < 2; ++mi) {
                uint32_t addr_h = smem_u32(&Ah_s[a_row + mi * 16][a_col + kk]);
                uint32_t addr_l = smem_u32(&Al_s[a_row + mi * 16][a_col + kk]);
                ldsm_x4(ah[mi][0], ah[mi][1], ah[mi][2], ah[mi][3], addr_h);
                ldsm_x4(al[mi][0], al[mi][1], al[mi][2], al[mi][3], addr_l);
            }
            uint32_t bh[4][2], bl[4][2];
#pragma unroll
            for (int p = 0; p < 2; ++p) {
                uint32_t r0, r1, r2, r3;
                uint32_t addr_h = smem_u32(&Bh_s[b_row + p * 16][b_col + kk]);
                ldsm_x4(r0, r1, r2, r3, addr_h);
                bh[p*2][0] = r0; bh[p*2][1] = r1; bh[p*2+1][0] = r2; bh[p*2+1][1] = r3;
                uint32_t addr_l = smem_u32(&Bl_s[b_row + p * 16][b_col + kk]);
                ldsm_x4(r0, r1, r2, r3, addr_l);
                bl[p*2][0] = r0; bl[p*2][1] = r1; bl[p*2+1][0] = r2; bl[p*2+1][1] = r3;
            }
#pragma unroll
            for (int mi = 0; mi < 2; ++mi)
#pragma unroll
                for (int nj = 0; nj < 4; ++nj) {
                    mma_bf16(acc[mi][nj], ah[mi][0], ah[mi][1], ah[mi][2], ah[mi][3],
                             bh[nj][0], bh[nj][1]);
                    mma_bf16(acc[mi][nj], ah[mi][0], ah[mi][1], ah[mi][2], ah[mi][3],
                             bl[nj][0], bl[nj][1]);
                    mma_bf16(acc[mi][nj], al[mi][0], al[mi][1], al[mi][2], al[mi][3],
                             bh[nj][0], bh[nj][1]);
                }
        }
    }

    int fr = lane >> 2, fc = (lane & 3) * 2;
#pragma unroll
    for (int mi = 0; mi < 2; ++mi) {
#pragma unroll
        for (int nj = 0; nj < 4; ++nj) {
            int gcol = colBase + wn * 32 + nj * 8 + fc;
            float bx = bias[gcol], by = bias[gcol + 1];
            int r0 = rowBase + wm * 32 + mi * 16 + fr;
            if (r0 < N) {
                float2 o = make_float2(acc[mi][nj][0] + bx, acc[mi][nj][1] + by);
                *(float2*)(C + (size_t)r0 * Mo + gcol) = o;
            }
            if (r0 + 8 < N) {
                float2 o = make_float2(acc[mi][nj][2] + bx, acc[mi][nj][3] + by);
                *(float2*)(C + (size_t)(r0 + 8) * Mo + gcol) = o;
            }
        }
    }
}

// ---- 4. conv1 aggregation: one warp per dst, 2-edge pipelined (R9) -----------
__global__ __launch_bounds__(256) void conv1_agg_kernel(
    const float* __restrict__ att1, int n)
{
    int gw = (blockIdx.x * blockDim.x + threadIdx.x) >> 5;
    int lane = threadIdx.x & 31;
    if (gw >= n) return;

    const float* xr_p = g_xlr1 + (size_t)gw * 576 + 256 + lane * 8;
    float4 xr0 = *(const float4*)xr_p;
    float4 xr1 = *(const float4*)(xr_p + 4);
    float4 at0 = *(const float4*)(att1 + lane * 8);
    float4 at1 = *(const float4*)(att1 + lane * 8 + 4);

    float den = 0.f;
    float acc[8];
#pragma unroll
    for (int j = 0; j < 8; j++) acc[j] = 0.f;

    int e0 = g_off[gw], e1 = g_off[gw + 1];
    int e = e0;
    for (; e + 2 <= e1; e += 2) {
        int s0 = g_esrc[e], s1 = g_esrc[e + 1];
        const float* pa = g_xlr1 + (size_t)s0 * 576 + lane * 8;
        const float* pb = g_xlr1 + (size_t)s1 * 576 + lane * 8;
        float4 xa0 = *(const float4*)pa;
        float4 xa1 = *(const float4*)(pa + 4);
        float4 xb0 = *(const float4*)pb;
        float4 xb1 = *(const float4*)(pb + 4);

        float p0, p1;
        p0  = at0.x * lrelu(xa0.x + xr0.x);
        p1  = at0.x * lrelu(xb0.x + xr0.x);
        p0 += at0.y * lrelu(xa0.y + xr0.y);
        p1 += at0.y * lrelu(xb0.y + xr0.y);
        p0 += at0.z * lrelu(xa0.z + xr0.z);
        p1 += at0.z * lrelu(xb0.z + xr0.z);
        p0 += at0.w * lrelu(xa0.w + xr0.w);
        p1 += at0.w * lrelu(xb0.w + xr0.w);
        p0 += at1.x * lrelu(xa1.x + xr1.x);
        p1 += at1.x * lrelu(xb1.x + xr1.x);
        p0 += at1.y * lrelu(xa1.y + xr1.y);
        p1 += at1.y * lrelu(xb1.y + xr1.y);
        p0 += at1.z * lrelu(xa1.z + xr1.z);
        p1 += at1.z * lrelu(xb1.z + xr1.z);
        p0 += at1.w * lrelu(xa1.w + xr1.w);
        p1 += at1.w * lrelu(xb1.w + xr1.w);

        p0 += __shfl_xor_sync(0xffffffffu, p0, 1);
        p1 += __shfl_xor_sync(0xffffffffu, p1, 1);
        p0 += __shfl_xor_sync(0xffffffffu, p0, 2);
        p1 += __shfl_xor_sync(0xffffffffu, p1, 2);
        p0 += __shfl_xor_sync(0xffffffffu, p0, 4);
        p1 += __shfl_xor_sync(0xffffffffu, p1, 4);

        float w0 = __expf(fminf(p0, 80.f));
        float w1 = __expf(fminf(p1, 80.f));
        den += w0 + w1;
        acc[0] += w0 * xa0.x + w1 * xb0.x;
        acc[1] += w0 * xa0.y + w1 * xb0.y;
        acc[2] += w0 * xa0.z + w1 * xb0.z;
        acc[3] += w0 * xa0.w + w1 * xb0.w;
        acc[4] += w0 * xa1.x + w1 * xb1.x;
        acc[5] += w0 * xa1.y + w1 * xb1.y;
        acc[6] += w0 * xa1.z + w1 * xb1.z;
        acc[7] += w0 * xa1.w + w1 * xb1.w;
    }
    if (e < e1) {
        int s = g_esrc[e];
        const float* pa = g_xlr1 + (size_t)s * 576 + lane * 8;
        float4 x0 = *(const float4*)pa;
        float4 x1 = *(const float4*)(pa + 4);
        float p;
        p  = at0.x * lrelu(x0.x + xr0.x);
        p += at0.y * lrelu(x0.y + xr0.y);
        p += at0.z * lrelu(x0.z + xr0.z);
        p += at0.w * lrelu(x0.w + xr0.w);
        p += at1.x * lrelu(x1.x + xr1.x);
        p += at1.y * lrelu(x1.y + xr1.y);
        p += at1.z * lrelu(x1.z + xr1.z);
        p += at1.w * lrelu(x1.w + xr1.w);
        p += __shfl_xor_sync(0xffffffffu, p, 1);
        p += __shfl_xor_sync(0xffffffffu, p, 2);
        p += __shfl_xor_sync(0xffffffffu, p, 4);
        float w = __expf(fminf(p, 80.f));
        den += w;
        acc[0] += w * x0.x; acc[1] += w * x0.y;
        acc[2] += w * x0.z; acc[3] += w * x0.w;
        acc[4] += w * x1.x; acc[5] += w * x1.y;
        acc[6] += w * x1.z; acc[7] += w * x1.w;
    }

    float inv = 1.f / den;
    int c = lane * 8;
    __nv_bfloat162 ph[4], pl[4];
#pragma unroll
    for (int j = 0; j < 4; ++j) {
        float v0 = fmaxf(acc[2*j]   * inv * g_c1a[c + 2*j]   + g_c1b[c + 2*j],   0.f);
        float v1 = fmaxf(acc[2*j+1] * inv * g_c1a[c + 2*j+1] + g_c1b[c + 2*j+1], 0.f);
        __nv_bfloat16 h0, l0, h1, l1;
        bf16_split(v0, h0, l0);
        bf16_split(v1, h1, l1);
        ph[j] = __nv_bfloat162(h0, h1);
        pl[j] = __nv_bfloat162(l0, l1);
    }
    *(uint4*)(g_hhi + (size_t)gw * 256 + c) = *(const uint4*)ph;
    *(uint4*)(g_hlo + (size_t)gw * 256 + c) = *(const uint4*)pl;
}

// ---- 6. conv2 aggregation + BN2 + relu + skip + head (R9 form) ----------------
__global__ __launch_bounds__(256) void conv2_agg_kernel(
    const float* __restrict__ att2, const float* __restrict__ Wo,
    const float* __restrict__ bo, float* __restrict__ out, int n)
{
    int gw = (blockIdx.x * blockDim.x + threadIdx.x) >> 5;
    int lane = threadIdx.x & 31;
    if (gw >= n) return;

    float2 xr = *(const float2*)(g_xlr2 + (size_t)gw * 128 + 64 + lane * 2);
    float2 at = *(const float2*)(att2 + lane * 2);

    float den = 0.f, a0 = 0.f, a1 = 0.f;

    int e0 = g_off[gw], e1 = g_off[gw + 1];
    int e = e0;
    for (; e + 2 <= e1; e += 2) {
        int s0 = g_esrc[e], s1 = g_esrc[e + 1];
        float2 xa = *(const float2*)(g_xlr2 + (size_t)s0 * 128 + lane * 2);
        float2 xb = *(const float2*)(g_xlr2 + (size_t)s1 * 128 + lane * 2);
        float p0 = at.x * lrelu(xa.x + xr.x) + at.y * lrelu(xa.y + xr.y);
        float p1 = at.x * lrelu(xb.x + xr.x) + at.y * lrelu(xb.y + xr.y);
        p0 += __shfl_xor_sync(0xffffffffu, p0, 1);
        p1 += __shfl_xor_sync(0xffffffffu, p1, 1);
        p0 += __shfl_xor_sync(0xffffffffu, p0, 2);
        p1 += __shfl_xor_sync(0xffffffffu, p1, 2);
        p0 += __shfl_xor_sync(0xffffffffu, p0, 4);
        p1 += __shfl_xor_sync(0xffffffffu, p1, 4);
        p0 += __shfl_xor_sync(0xffffffffu, p0, 8);
        p1 += __shfl_xor_sync(0xffffffffu, p1, 8);
        p0 += __shfl_xor_sync(0xffffffffu, p0, 16);
        p1 += __shfl_xor_sync(0xffffffffu, p1, 16);
        float w0 = __expf(fminf(p0, 80.f));
        float w1 = __expf(fminf(p1, 80.f));
        den += w0 + w1;
        a0 += w0 * xa.x + w1 * xb.x;
        a1 += w0 * xa.y + w1 * xb.y;
    }
    if (e < e1) {
        int s = g_esrc[e];
        float2 x = *(const float2*)(g_xlr2 + (size_t)s * 128 + lane * 2);
        float p = at.x * lrelu(x.x + xr.x) + at.y * lrelu(x.y + xr.y);
        p += __shfl_xor_sync(0xffffffffu, p, 1);
        p += __shfl_xor_sync(0xffffffffu, p, 2);
        p += __shfl_xor_sync(0xffffffffu, p, 4);
        p += __shfl_xor_sync(0xffffffffu, p, 8);
        p += __shfl_xor_sync(0xffffffffu, p, 16);
        float w = __expf(fminf(p, 80.f));
        den += w;
        a0 += w * x.x;
        a1 += w * x.y;
    }

    float inv = 1.f / den;
    int c = lane * 2;
    float2 sk = *(const float2*)(g_xlr1 + (size_t)gw * 576 + 512 + c);
    float h0 = fmaxf(a0 * inv * g_c2a[c + 0] + g_c2b[c + 0], 0.f) + sk.x;
    float h1 = fmaxf(a1 * inv * g_c2a[c + 1] + g_c2b[c + 1], 0.f) + sk.y;

    float r = h0 * Wo[c] + h1 * Wo[c + 1];
    r += __shfl_xor_sync(0xffffffffu, r, 1);
    r += __shfl_xor_sync(0xffffffffu, r, 2);
    r += __shfl_xor_sync(0xffffffffu, r, 4);
    r += __shfl_xor_sync(0xffffffffu, r, 8);
    r += __shfl_xor_sync(0xffffffffu, r, 16);
    if (lane == 0) out[gw] = r + bo[0];
}

// ---- host --------------------------------------------------------------------
extern "C" void kernel_launch(void* const* d_in, const int* in_sizes, int n_in,
                              void* d_out, int out_size)
{
    const float* x     = (const float*)d_in[0];
    const int*   ei    = (const int*)d_in[1];
    const float* Wl1   = (const float*)d_in[2];
    const float* bl1   = (const float*)d_in[3];
    const float* Wr1   = (const float*)d_in[4];
    const float* br1   = (const float*)d_in[5];
    const float* att1  = (const float*)d_in[6];
    const float* bias1 = (const float*)d_in[7];
    const float* g1    = (const float*)d_in[8];
    const float* b1    = (const float*)d_in[9];
    const float* m1    = (const float*)d_in[10];
    const float* v1    = (const float*)d_in[11];
    const float* Wl2   = (const float*)d_in[12];
    const float* bl2   = (const float*)d_in[13];
    const float* Wr2   = (const float*)d_in[14];
    const float* br2   = (const float*)d_in[15];
    const float* att2  = (const float*)d_in[16];
    const float* bias2 = (const float*)d_in[17];
    const float* g2    = (const float*)d_in[18];
    const float* b2    = (const float*)d_in[19];
    const float* m2    = (const float*)d_in[20];
    const float* v2    = (const float*)d_in[21];
    const float* Ws    = (const float*)d_in[22];
    const float* bs    = (const float*)d_in[23];
    const float* Wo    = (const float*)d_in[24];
    const float* bo    = (const float*)d_in[25];

    int n = in_sizes[0] / 160;
    int e = in_sizes[1] / 2;
    int nblk = (n + 1023) / 1024;
    int e4 = (e + 3) / 4;

    static cudaStream_t s_side = nullptr;
    static cudaEvent_t ev_fork = nullptr, ev_join = nullptr;
    if (!s_side) {
        cudaStreamCreateWithFlags(&s_side, cudaStreamNonBlocking);
        cudaEventCreateWithFlags(&ev_fork, cudaEventDisableTiming);
        cudaEventCreateWithFlags(&ev_join, cudaEventDisableTiming);
    }

    // fork: CSR build on side stream, overlapped with prep + GEMM1
    cudaEventRecord(ev_fork, 0);
    cudaStreamWaitEvent(s_side, ev_fork, 0);

    count_kernel  <<<(e4 + 255) / 256, 256, 0, s_side>>>(ei, e, n);
    scan1_kernel  <<<nblk, 1024, 0, s_side>>>(n);
    scan2_kernel  <<<1, 64, 0, s_side>>>(nblk);
    scan3sl_kernel<<<nblk, 1024, 0, s_side>>>(n);
    scatter_kernel<<<(e4 + 255) / 256, 256, 0, s_side>>>(ei, e, n);
    cudaEventRecord(ev_join, s_side);

    // main: prep -> GEMM1 (fused x split)
    prep_kernel<<<(125952 + 255) / 256, 256>>>(
        Wl1, bl1, Wr1, br1, Ws, bs, Wl2, bl2, Wr2, br2,
        bias1, g1, b1, m1, v1, bias2, g2, b2, m2, v2);
    {
        dim3 grid(576 / 64, (n + 127) / 128);
        gemm_mma_kernel<0><<<grid, 256>>>(x, n);
    }

    cudaStreamWaitEvent(0, ev_join, 0);

    conv1_agg_kernel<<<(n + 7) / 8, 256>>>(att1, n);
    {
        dim3 grid(128 / 64, (n + 127) / 128);
        gemm_mma_kernel<1><<<grid, 256>>>(nullptr, n);
    }
    conv2_agg_kernel<<<(n + 7) / 8, 256>>>(att2, Wo, bo, (float*)d_out, n);
}

// round 15
// speedup vs baseline: 1.1184x; 1.0240x over previous
#include <cuda_runtime.h>
#include <cuda_bf16.h>
#include <cstdint>

// ============================================================================
// GATv2 x2 + BN + skip + linear head.
// R15: GEMMs get cp.async (LDGSTS) double-buffered smem fills — loads for
// chunk k+1 stream global->smem asynchronously (no register residency, the
// failure mode of R10/R13) while MMA consumes chunk k. x is pre-split to
// bf16 hi/lo once (xconv, side stream, hidden under prep). All other kernels
// byte-identical to R14 (352.1us best).
// GEMMs: HMMA bf16 2-term split (hi*hi+hi*lo+lo*hi, fp32 acc); tcgen05 is
// unavailable (harness compiles through compute_103 PTX which rejects it).
// ============================================================================

#define NEG_SLOPE 0.2f

static constexpr int NMAX  = 50000;
static constexpr int EMAX  = 800000;
static constexpr int EPMAX = EMAX + NMAX;

static constexpr int K1 = 160;
static constexpr int K2 = 256;

// ---- scratch ---------------------------------------------------------------
__device__ float          g_xlr1[(size_t)NMAX * 576]; // xl1|xr1|skip (fp32)
__device__ float          g_xlr2[(size_t)NMAX * 128]; // xl2|xr2      (fp32)
__device__ __nv_bfloat16  g_xhi [(size_t)NMAX * K1];
__device__ __nv_bfloat16  g_xlo [(size_t)NMAX * K1];
__device__ __nv_bfloat16  g_hhi [(size_t)NMAX * K2];
__device__ __nv_bfloat16  g_hlo [(size_t)NMAX * K2];
__device__ int   g_deg [NMAX];       // zero at entry; re-zeroed by scan1
__device__ int   g_off [NMAX + 1];
__device__ int   g_cur [NMAX];
__device__ int   g_esrc[EPMAX];
__device__ int   g_bsum[64];
__device__ __nv_bfloat16 g_W1thi[576 * K1];
__device__ __nv_bfloat16 g_W1tlo[576 * K1];
__device__ __nv_bfloat16 g_W2thi[128 * K2];
__device__ __nv_bfloat16 g_W2tlo[128 * K2];
__device__ float g_b1c [576];
__device__ float g_b2c [128];
__device__ float g_c1a [256];
__device__ float g_c1b [256];
__device__ float g_c2a [64];
__device__ float g_c2b [64];

// ---- helpers ----------------------------------------------------------------
__device__ __forceinline__ uint32_t smem_u32(const void* p) {
    uint32_t a;
    asm("{ .reg .u64 t; cvta.to.shared.u64 t, %1; cvt.u32.u64 %0, t; }"
        : "=r"(a) : "l"(p));
    return a;
}
__device__ __forceinline__ void ldsm_x4(uint32_t& r0, uint32_t& r1,
                                        uint32_t& r2, uint32_t& r3, uint32_t a) {
    asm volatile("ldmatrix.sync.aligned.m8n8.x4.shared.b16 {%0,%1,%2,%3}, [%4];"
                 : "=r"(r0), "=r"(r1), "=r"(r2), "=r"(r3) : "r"(a));
}
__device__ __forceinline__ void mma_bf16(float* c, uint32_t a0, uint32_t a1,
                                         uint32_t a2, uint32_t a3,
                                         uint32_t b0, uint32_t b1) {
    asm volatile(
        "mma.sync.aligned.m16n8k16.row.col.f32.bf16.bf16.f32 "
        "{%0,%1,%2,%3}, {%4,%5,%6,%7}, {%8,%9}, {%0,%1,%2,%3};"
        : "+f"(c[0]), "+f"(c[1]), "+f"(c[2]), "+f"(c[3])
        : "r"(a0), "r"(a1), "r"(a2), "r"(a3), "r"(b0), "r"(b1));
}
__device__ __forceinline__ void cp16(uint32_t dst, const void* src, int srcsz) {
    asm volatile("cp.async.cg.shared.global [%0], [%1], 16, %2;"
                 :: "r"(dst), "l"(src), "r"(srcsz) : "memory");
}
#define CP_COMMIT() asm volatile("cp.async.commit_group;" ::: "memory")
__device__ __forceinline__ void bf16_split(float v, __nv_bfloat16& hi, __nv_bfloat16& lo) {
    hi = __float2bfloat16(v);
    lo = __float2bfloat16(v - __bfloat162float(hi));
}
__device__ __forceinline__ float lrelu(float t) {
    return fmaxf(t, 0.f) + NEG_SLOPE * fminf(t, 0.f);
}

// ---- 1. prep (combined, main stream) ------------------------------------------
__global__ void prep_kernel(
    const float* __restrict__ Wl1, const float* __restrict__ bl1,
    const float* __restrict__ Wr1, const float* __restrict__ br1,
    const float* __restrict__ Ws,  const float* __restrict__ bs,
    const float* __restrict__ Wl2, const float* __restrict__ bl2,
    const float* __restrict__ Wr2, const float* __restrict__ br2,
    const float* __restrict__ bias1, const float* __restrict__ g1,
    const float* __restrict__ b1,  const float* __restrict__ m1,
    const float* __restrict__ v1,
    const float* __restrict__ bias2, const float* __restrict__ g2,
    const float* __restrict__ b2,  const float* __restrict__ m2,
    const float* __restrict__ v2)
{
    int i = blockIdx.x * blockDim.x + threadIdx.x;
    if (i < 92160) {
        int nidx = i / K1, k = i % K1;
        float v;
        if (nidx < 256)      v = Wl1[k * 256 + nidx];
        else if (nidx < 512) v = Wr1[k * 256 + (nidx - 256)];
        else                 v = Ws [k * 64  + (nidx - 512)];
        __nv_bfloat16 hi, lo; bf16_split(v, hi, lo);
        g_W1thi[i] = hi; g_W1tlo[i] = lo;
    } else if (i < 92736) {
        int m = i - 92160;
        g_b1c[m] = (m < 256) ? bl1[m] : ((m < 512) ? br1[m - 256] : bs[m - 512]);
    } else if (i < 125504) {
        int j = i - 92736;
        int nidx = j / K2, k = j % K2;
        float v = (nidx < 64) ? Wl2[k * 64 + nidx] : Wr2[k * 64 + (nidx - 64)];
        __nv_bfloat16 hi, lo; bf16_split(v, hi, lo);
        g_W2thi[j] = hi; g_W2tlo[j] = lo;
    } else if (i < 125632) {
        int m = i - 125504;
        g_b2c[m] = (m < 64) ? bl2[m] : br2[m - 64];
    } else if (i < 125888) {
        int j = i - 125632;
        float sc = g1[j] * rsqrtf(v1[j] + 1e-5f);
        g_c1a[j] = sc;
        g_c1b[j] = (bias1[j] - m1[j]) * sc + b1[j];
    } else if (i < 125952) {
        int j = i - 125888;
        float sc = g2[j] * rsqrtf(v2[j] + 1e-5f);
        g_c2a[j] = sc;
        g_c2b[j] = (bias2[j] - m2[j]) * sc + b2[j];
    }
}

// ---- 1b. x -> bf16 hi/lo (side stream, hidden under prep) ---------------------
__global__ void xconv_kernel(const float* __restrict__ x, int n) {
    int i = blockIdx.x * blockDim.x + threadIdx.x;
    if (i < n * K1) {
        float v = x[i];
        __nv_bfloat16 hi, lo; bf16_split(v, hi, lo);
        g_xhi[i] = hi; g_xlo[i] = lo;
    }
}

// ---- 2. CSR build (side stream; merged kernels) -------------------------------
__global__ void count_kernel(const int* __restrict__ ei, int e, int n) {
    int i = (blockIdx.x * blockDim.x + threadIdx.x) * 4;
    if (i + 3 < e) {
        int4 d = *(const int4*)(ei + e + i);
        if ((unsigned)d.x < (unsigned)n) atomicAdd(&g_deg[d.x], 1);
        if ((unsigned)d.y < (unsigned)n) atomicAdd(&g_deg[d.y], 1);
        if ((unsigned)d.z < (unsigned)n) atomicAdd(&g_deg[d.z], 1);
        if ((unsigned)d.w < (unsigned)n) atomicAdd(&g_deg[d.w], 1);
    } else {
        for (int j = i; j < e; ++j) {
            int d = ei[e + j];
            if ((unsigned)d < (unsigned)n) atomicAdd(&g_deg[d], 1);
        }
    }
}
__global__ void scan1_kernel(int n) {
    __shared__ int sh[1024];
    int tid = threadIdx.x;
    int i = blockIdx.x * 1024 + tid;
    int v = 0;
    if (i < n) {
        v = g_deg[i] + 1;
        g_deg[i] = 0;
        g_cur[i] = v;
    }
    sh[tid] = v;
    __syncthreads();
#pragma unroll
    for (int off = 1; off < 1024; off <<= 1) {
        int t = (tid >= off) ? sh[tid - off] : 0;
        __syncthreads();
        sh[tid] += t;
        __syncthreads();
    }
    if (i < n) g_off[i + 1] = sh[tid];
    if (tid == 1023) g_bsum[blockIdx.x] = sh[1023];
}
__global__ void scan2_kernel(int nblk) {
    __shared__ int sh[64];
    int tid = threadIdx.x;
    int v = (tid < nblk) ? g_bsum[tid] : 0;
    sh[tid] = v;
    __syncthreads();
#pragma unroll
    for (int off = 1; off < 64; off <<= 1) {
        int t = (tid >= off) ? sh[tid - off] : 0;
        __syncthreads();
        sh[tid] += t;
        __syncthreads();
    }
    if (tid < nblk) g_bsum[tid] = sh[tid] - v;
}
__global__ void scan3sl_kernel(int n) {
    int tid = threadIdx.x;
    int i = blockIdx.x * 1024 + tid;
    if (blockIdx.x == 0 && tid == 0) g_off[0] = 0;
    if (i < n) {
        int add = (blockIdx.x > 0) ? g_bsum[blockIdx.x] : 0;
        int fin = g_off[i + 1] + add;
        g_off[i + 1] = fin;
        int o = fin - g_cur[i];
        g_esrc[o] = i;
        g_cur[i] = o + 1;
    }
}
__global__ void scatter_kernel(const int* __restrict__ ei, int e, int n) {
    int i = (blockIdx.x * blockDim.x + threadIdx.x) * 4;
    if (i + 3 < e) {
        int4 s = *(const int4*)(ei + i);
        int4 d = *(const int4*)(ei + e + i);
        if ((unsigned)s.x < (unsigned)n && (unsigned)d.x < (unsigned)n)
            g_esrc[atomicAdd(&g_cur[d.x], 1)] = s.x;
        if ((unsigned)s.y < (unsigned)n && (unsigned)d.y < (unsigned)n)
            g_esrc[atomicAdd(&g_cur[d.y], 1)] = s.y;
        if ((unsigned)s.z < (unsigned)n && (unsigned)d.z < (unsigned)n)
            g_esrc[atomicAdd(&g_cur[d.z], 1)] = s.z;
        if ((unsigned)s.w < (unsigned)n && (unsigned)d.w < (unsigned)n)
            g_esrc[atomicAdd(&g_cur[d.w], 1)] = s.w;
    } else {
        for (int j = i; j < e; ++j) {
            int s = ei[j], d = ei[e + j];
            if ((unsigned)s < (unsigned)n && (unsigned)d < (unsigned)n)
                g_esrc[atomicAdd(&g_cur[d], 1)] = s;
        }
    }
}

// ---- 3/5. HMMA bf16-split GEMM, cp.async double-buffered ----------------------
// CTA 128x64, 8 warps, 32x32 warp tile (R9 MMA structure).
// Smem per buffer: Ah 10240 | Al 10240 | Bh 5120 | Bl 5120 = 30720 B; x2 bufs.
// MODE 0: A = g_xhi/g_xlo, K=160, Mo=576;  MODE 1: A = g_hhi/g_hlo, K=256, Mo=128
template <int MODE>
__global__ __launch_bounds__(256) void gemm_mma_kernel(int N)
{
    constexpr int K   = (MODE == 0) ? K1 : K2;
    constexpr int Mo  = (MODE == 0) ? 576 : 128;
    constexpr int C   = K / 32;
    constexpr int BUF = 30720;
    constexpr int O_AL = 10240, O_BH = 20480, O_BL = 25600;

    const __nv_bfloat16* __restrict__ Ahi = (MODE == 0) ? g_xhi : g_hhi;
    const __nv_bfloat16* __restrict__ Alo = (MODE == 0) ? g_xlo : g_hlo;
    const __nv_bfloat16* __restrict__ Bhi = (MODE == 0) ? g_W1thi : g_W2thi;
    const __nv_bfloat16* __restrict__ Blo = (MODE == 0) ? g_W1tlo : g_W2tlo;
    const float* __restrict__ bias = (MODE == 0) ? g_b1c : g_b2c;
    float* __restrict__ C_out      = (MODE == 0) ? g_xlr1 : g_xlr2;

    extern __shared__ char smem_raw[];
    uint32_t sb = smem_u32(smem_raw);

    int tid  = threadIdx.x;
    int wid  = tid >> 5, lane = tid & 31;
    int wm   = wid & 3;
    int wn   = wid >> 2;
    int rowBase = blockIdx.y * 128, colBase = blockIdx.x * 64;

    // fill mapping (fixed per thread)
    int ar = tid >> 1, ahalf = tid & 1;
    int agrow = rowBase + ar;
    int aok = (agrow < N) ? 16 : 0;
    const __nv_bfloat16* pah_base = Ahi + (size_t)agrow * K + ahalf * 16;
    const __nv_bfloat16* pal_base = Alo + (size_t)agrow * K + ahalf * 16;
    uint32_t da_off = (uint32_t)(ar * 80 + ahalf * 32);
    int br_ = tid >> 2, bq = tid & 3;
    const __nv_bfloat16* pbh_base = Bhi + (size_t)(colBase + br_) * K + bq * 8;
    const __nv_bfloat16* pbl_base = Blo + (size_t)(colBase + br_) * K + bq * 8;
    uint32_t db_off = (uint32_t)(br_ * 80 + bq * 16);

    float acc[2][4][4];
#pragma unroll
    for (int i = 0; i < 2; i++)
#pragma unroll
        for (int j = 0; j < 4; j++)
#pragma unroll
            for (int q = 0; q < 4; q++) acc[i][j][q] = 0.f;

    int sel = lane >> 3;
    int a_row = wm * 32 + (lane & 7) + (sel & 1) * 8;
    int a_col = (sel >> 1) * 8;
    int b_row = wn * 32 + (lane & 7) + (sel >> 1) * 8;
    int b_col = (sel & 1) * 8;

    auto fill = [&](int c, int b) {
        int k0 = c * 32;
        uint32_t base = sb + b * BUF;
        cp16(base + da_off,               pah_base + k0,     aok);
        cp16(base + da_off + 16,          pah_base + k0 + 8, aok);
        cp16(base + O_AL + da_off,        pal_base + k0,     aok);
        cp16(base + O_AL + da_off + 16,   pal_base + k0 + 8, aok);
        cp16(base + O_BH + db_off,        pbh_base + k0,     16);
        cp16(base + O_BL + db_off,        pbl_base + k0,     16);
        CP_COMMIT();
    };

    fill(0, 0);
    for (int c = 0; c < C; ++c) {
        int b = c & 1;
        if (c + 1 < C) {
            fill(c + 1, b ^ 1);
            asm volatile("cp.async.wait_group 1;" ::: "memory");
        } else {
            asm volatile("cp.async.wait_group 0;" ::: "memory");
        }
        __syncthreads();

        uint32_t abase = sb + b * BUF;
#pragma unroll
        for (int kk = 0; kk < 32; kk += 16) {
            uint32_t ah[2][4], al[2][4];
#pragma unroll
            for (int mi = 0; mi < 2; ++mi) {
                uint32_t addr_h = abase + (uint32_t)((a_row + mi * 16) * 80 + (a_col + kk) * 2);
                uint32_t addr_l = addr_h + O_AL;
                ldsm_x4(ah[mi][0], ah[mi][1], ah[mi][2], ah[mi][3], addr_h);
                ldsm_x4(al[mi][0], al[mi][1], al[mi][2], al[mi][3], addr_l);
            }
            uint32_t bh[4][2], bl[4][2];
#pragma unroll
            for (int p = 0; p < 2; ++p) {
                uint32_t r0, r1, r2, r3;
                uint32_t addr_h = abase + O_BH + (uint32_t)((b_row + p * 16) * 80 + (b_col + kk) * 2);
                ldsm_x4(r0, r1, r2, r3, addr_h);
                bh[p*2][0] = r0; bh[p*2][1] = r1; bh[p*2+1][0] = r2; bh[p*2+1][1] = r3;
                uint32_t addr_l = addr_h + (O_BL - O_BH);
                ldsm_x4(r0, r1, r2, r3, addr_l);
                bl[p*2][0] = r0; bl[p*2][1] = r1; bl[p*2+1][0] = r2; bl[p*2+1][1] = r3;
            }
#pragma unroll
            for (int mi = 0; mi < 2; ++mi)
#pragma unroll
                for (int nj = 0; nj < 4; ++nj) {
                    mma_bf16(acc[mi][nj], ah[mi][0], ah[mi][1], ah[mi][2], ah[mi][3],
                             bh[nj][0], bh[nj][1]);
                    mma_bf16(acc[mi][nj], ah[mi][0], ah[mi][1], ah[mi][2], ah[mi][3],
                             bl[nj][0], bl[nj][1]);
                    mma_bf16(acc[mi][nj], al[mi][0], al[mi][1], al[mi][2], al[mi][3],
                             bh[nj][0], bh[nj][1]);
                }
        }
        __syncthreads();
    }

    int fr = lane >> 2, fc = (lane & 3) * 2;
#pragma unroll
    for (int mi = 0; mi < 2; ++mi) {
#pragma unroll
        for (int nj = 0; nj < 4; ++nj) {
            int gcol = colBase + wn * 32 + nj * 8 + fc;
            float bx = bias[gcol], by = bias[gcol + 1];
            int r0 = rowBase + wm * 32 + mi * 16 + fr;
            if (r0 < N) {
                float2 o = make_float2(acc[mi][nj][0] + bx, acc[mi][nj][1] + by);
                *(float2*)(C_out + (size_t)r0 * Mo + gcol) = o;
            }
            if (r0 + 8 < N) {
                float2 o = make_float2(acc[mi][nj][2] + bx, acc[mi][nj][3] + by);
                *(float2*)(C_out + (size_t)(r0 + 8) * Mo + gcol) = o;
            }
        }
    }
}

// ---- 4. conv1 aggregation: one warp per dst, 2-edge pipelined (R9) -----------
__global__ __launch_bounds__(256) void conv1_agg_kernel(
    const float* __restrict__ att1, int n)
{
    int gw = (blockIdx.x * blockDim.x + threadIdx.x) >> 5;
    int lane = threadIdx.x & 31;
    if (gw >= n) return;

    const float* xr_p = g_xlr1 + (size_t)gw * 576 + 256 + lane * 8;
    float4 xr0 = *(const float4*)xr_p;
    float4 xr1 = *(const float4*)(xr_p + 4);
    float4 at0 = *(const float4*)(att1 + lane * 8);
    float4 at1 = *(const float4*)(att1 + lane * 8 + 4);

    float den = 0.f;
    float acc[8];
#pragma unroll
    for (int j = 0; j < 8; j++) acc[j] = 0.f;

    int e0 = g_off[gw], e1 = g_off[gw + 1];
    int e = e0;
    for (; e + 2 <= e1; e += 2) {
        int s0 = g_esrc[e], s1 = g_esrc[e + 1];
        const float* pa = g_xlr1 + (size_t)s0 * 576 + lane * 8;
        const float* pb = g_xlr1 + (size_t)s1 * 576 + lane * 8;
        float4 xa0 = *(const float4*)pa;
        float4 xa1 = *(const float4*)(pa + 4);
        float4 xb0 = *(const float4*)pb;
        float4 xb1 = *(const float4*)(pb + 4);

        float p0, p1;
        p0  = at0.x * lrelu(xa0.x + xr0.x);
        p1  = at0.x * lrelu(xb0.x + xr0.x);
        p0 += at0.y * lrelu(xa0.y + xr0.y);
        p1 += at0.y * lrelu(xb0.y + xr0.y);
        p0 += at0.z * lrelu(xa0.z + xr0.z);
        p1 += at0.z * lrelu(xb0.z + xr0.z);
        p0 += at0.w * lrelu(xa0.w + xr0.w);
        p1 += at0.w * lrelu(xb0.w + xr0.w);
        p0 += at1.x * lrelu(xa1.x + xr1.x);
        p1 += at1.x * lrelu(xb1.x + xr1.x);
        p0 += at1.y * lrelu(xa1.y + xr1.y);
        p1 += at1.y * lrelu(xb1.y + xr1.y);
        p0 += at1.z * lrelu(xa1.z + xr1.z);
        p1 += at1.z * lrelu(xb1.z + xr1.z);
        p0 += at1.w * lrelu(xa1.w + xr1.w);
        p1 += at1.w * lrelu(xb1.w + xr1.w);

        p0 += __shfl_xor_sync(0xffffffffu, p0, 1);
        p1 += __shfl_xor_sync(0xffffffffu, p1, 1);
        p0 += __shfl_xor_sync(0xffffffffu, p0, 2);
        p1 += __shfl_xor_sync(0xffffffffu, p1, 2);
        p0 += __shfl_xor_sync(0xffffffffu, p0, 4);
        p1 += __shfl_xor_sync(0xffffffffu, p1, 4);

        float w0 = __expf(fminf(p0, 80.f));
        float w1 = __expf(fminf(p1, 80.f));
        den += w0 + w1;
        acc[0] += w0 * xa0.x + w1 * xb0.x;
        acc[1] += w0 * xa0.y + w1 * xb0.y;
        acc[2] += w0 * xa0.z + w1 * xb0.z;
        acc[3] += w0 * xa0.w + w1 * xb0.w;
        acc[4] += w0 * xa1.x + w1 * xb1.x;
        acc[5] += w0 * xa1.y + w1 * xb1.y;
        acc[6] += w0 * xa1.z + w1 * xb1.z;
        acc[7] += w0 * xa1.w + w1 * xb1.w;
    }
    if (e < e1) {
        int s = g_esrc[e];
        const float* pa = g_xlr1 + (size_t)s * 576 + lane * 8;
        float4 x0 = *(const float4*)pa;
        float4 x1 = *(const float4*)(pa + 4);
        float p;
        p  = at0.x * lrelu(x0.x + xr0.x);
        p += at0.y * lrelu(x0.y + xr0.y);
        p += at0.z * lrelu(x0.z + xr0.z);
        p += at0.w * lrelu(x0.w + xr0.w);
        p += at1.x * lrelu(x1.x + xr1.x);
        p += at1.y * lrelu(x1.y + xr1.y);
        p += at1.z * lrelu(x1.z + xr1.z);
        p += at1.w * lrelu(x1.w + xr1.w);
        p += __shfl_xor_sync(0xffffffffu, p, 1);
        p += __shfl_xor_sync(0xffffffffu, p, 2);
        p += __shfl_xor_sync(0xffffffffu, p, 4);
        float w = __expf(fminf(p, 80.f));
        den += w;
        acc[0] += w * x0.x; acc[1] += w * x0.y;
        acc[2] += w * x0.z; acc[3] += w * x0.w;
        acc[4] += w * x1.x; acc[5] += w * x1.y;
        acc[6] += w * x1.z; acc[7] += w * x1.w;
    }

    float inv = 1.f / den;
    int c = lane * 8;
    __nv_bfloat162 ph[4], pl[4];
#pragma unroll
    for (int j = 0; j < 4; ++j) {
        float v0 = fmaxf(acc[2*j]   * inv * g_c1a[c + 2*j]   + g_c1b[c + 2*j],   0.f);
        float v1 = fmaxf(acc[2*j+1] * inv * g_c1a[c + 2*j+1] + g_c1b[c + 2*j+1], 0.f);
        __nv_bfloat16 h0, l0, h1, l1;
        bf16_split(v0, h0, l0);
        bf16_split(v1, h1, l1);
        ph[j] = __nv_bfloat162(h0, h1);
        pl[j] = __nv_bfloat162(l0, l1);
    }
    *(uint4*)(g_hhi + (size_t)gw * 256 + c) = *(const uint4*)ph;
    *(uint4*)(g_hlo + (size_t)gw * 256 + c) = *(const uint4*)pl;
}

// ---- 6. conv2 aggregation + BN2 + relu + skip + head (R9 form) ----------------
__global__ __launch_bounds__(256) void conv2_agg_kernel(
    const float* __restrict__ att2, const float* __restrict__ Wo,
    const float* __restrict__ bo, float* __restrict__ out, int n)
{
    int gw = (blockIdx.x * blockDim.x + threadIdx.x) >> 5;
    int lane = threadIdx.x & 31;
    if (gw >= n) return;

    float2 xr = *(const float2*)(g_xlr2 + (size_t)gw * 128 + 64 + lane * 2);
    float2 at = *(const float2*)(att2 + lane * 2);

    float den = 0.f, a0 = 0.f, a1 = 0.f;

    int e0 = g_off[gw], e1 = g_off[gw + 1];
    int e = e0;
    for (; e + 2 <= e1; e += 2) {
        int s0 = g_esrc[e], s1 = g_esrc[e + 1];
        float2 xa = *(const float2*)(g_xlr2 + (size_t)s0 * 128 + lane * 2);
        float2 xb = *(const float2*)(g_xlr2 + (size_t)s1 * 128 + lane * 2);
        float p0 = at.x * lrelu(xa.x + xr.x) + at.y * lrelu(xa.y + xr.y);
        float p1 = at.x * lrelu(xb.x + xr.x) + at.y * lrelu(xb.y + xr.y);
        p0 += __shfl_xor_sync(0xffffffffu, p0, 1);
        p1 += __shfl_xor_sync(0xffffffffu, p1, 1);
        p0 += __shfl_xor_sync(0xffffffffu, p0, 2);
        p1 += __shfl_xor_sync(0xffffffffu, p1, 2);
        p0 += __shfl_xor_sync(0xffffffffu, p0, 4);
        p1 += __shfl_xor_sync(0xffffffffu, p1, 4);
        p0 += __shfl_xor_sync(0xffffffffu, p0, 8);
        p1 += __shfl_xor_sync(0xffffffffu, p1, 8);
        p0 += __shfl_xor_sync(0xffffffffu, p0, 16);
        p1 += __shfl_xor_sync(0xffffffffu, p1, 16);
        float w0 = __expf(fminf(p0, 80.f));
        float w1 = __expf(fminf(p1, 80.f));
        den += w0 + w1;
        a0 += w0 * xa.x + w1 * xb.x;
        a1 += w0 * xa.y + w1 * xb.y;
    }
    if (e < e1) {
        int s = g_esrc[e];
        float2 x = *(const float2*)(g_xlr2 + (size_t)s * 128 + lane * 2);
        float p = at.x * lrelu(x.x + xr.x) + at.y * lrelu(x.y + xr.y);
        p += __shfl_xor_sync(0xffffffffu, p, 1);
        p += __shfl_xor_sync(0xffffffffu, p, 2);
        p += __shfl_xor_sync(0xffffffffu, p, 4);
        p += __shfl_xor_sync(0xffffffffu, p, 8);
        p += __shfl_xor_sync(0xffffffffu, p, 16);
        float w = __expf(fminf(p, 80.f));
        den += w;
        a0 += w * x.x;
        a1 += w * x.y;
    }

    float inv = 1.f / den;
    int c = lane * 2;
    float2 sk = *(const float2*)(g_xlr1 + (size_t)gw * 576 + 512 + c);
    float h0 = fmaxf(a0 * inv * g_c2a[c + 0] + g_c2b[c + 0], 0.f) + sk.x;
    float h1 = fmaxf(a1 * inv * g_c2a[c + 1] + g_c2b[c + 1], 0.f) + sk.y;

    float r = h0 * Wo[c] + h1 * Wo[c + 1];
    r += __shfl_xor_sync(0xffffffffu, r, 1);
    r += __shfl_xor_sync(0xffffffffu, r, 2);
    r += __shfl_xor_sync(0xffffffffu, r, 4);
    r += __shfl_xor_sync(0xffffffffu, r, 8);
    r += __shfl_xor_sync(0xffffffffu, r, 16);
    if (lane == 0) out[gw] = r + bo[0];
}

// ---- host --------------------------------------------------------------------
extern "C" void kernel_launch(void* const* d_in, const int* in_sizes, int n_in,
                              void* d_out, int out_size)
{
    const float* x     = (const float*)d_in[0];
    const int*   ei    = (const int*)d_in[1];
    const float* Wl1   = (const float*)d_in[2];
    const float* bl1   = (const float*)d_in[3];
    const float* Wr1   = (const float*)d_in[4];
    const float* br1   = (const float*)d_in[5];
    const float* att1  = (const float*)d_in[6];
    const float* bias1 = (const float*)d_in[7];
    const float* g1    = (const float*)d_in[8];
    const float* b1    = (const float*)d_in[9];
    const float* m1    = (const float*)d_in[10];
    const float* v1    = (const float*)d_in[11];
    const float* Wl2   = (const float*)d_in[12];
    const float* bl2   = (const float*)d_in[13];
    const float* Wr2   = (const float*)d_in[14];
    const float* br2   = (const float*)d_in[15];
    const float* att2  = (const float*)d_in[16];
    const float* bias2 = (const float*)d_in[17];
    const float* g2    = (const float*)d_in[18];
    const float* b2    = (const float*)d_in[19];
    const float* m2    = (const float*)d_in[20];
    const float* v2    = (const float*)d_in[21];
    const float* Ws    = (const float*)d_in[22];
    const float* bs    = (const float*)d_in[23];
    const float* Wo    = (const float*)d_in[24];
    const float* bo    = (const float*)d_in[25];

    int n = in_sizes[0] / 160;
    int e = in_sizes[1] / 2;
    int nblk = (n + 1023) / 1024;
    int e4 = (e + 3) / 4;

    constexpr int GEMM_SMEM = 2 * 30720;   // 61440 B

    static cudaStream_t s_side = nullptr;
    static cudaEvent_t ev_x = nullptr, ev_fork = nullptr, ev_join = nullptr;
    if (!s_side) {
        cudaStreamCreateWithFlags(&s_side, cudaStreamNonBlocking);
        cudaEventCreateWithFlags(&ev_x,    cudaEventDisableTiming);
        cudaEventCreateWithFlags(&ev_fork, cudaEventDisableTiming);
        cudaEventCreateWithFlags(&ev_join, cudaEventDisableTiming);
        cudaFuncSetAttribute(gemm_mma_kernel<0>,
                             cudaFuncAttributeMaxDynamicSharedMemorySize, GEMM_SMEM);
        cudaFuncSetAttribute(gemm_mma_kernel<1>,
                             cudaFuncAttributeMaxDynamicSharedMemorySize, GEMM_SMEM);
    }

    // fork: xconv first (GEMM1 dep), then CSR build on side stream
    cudaEventRecord(ev_fork, 0);
    cudaStreamWaitEvent(s_side, ev_fork, 0);

    xconv_kernel  <<<(n * K1 + 255) / 256, 256, 0, s_side>>>(x, n);
    cudaEventRecord(ev_x, s_side);
    count_kernel  <<<(e4 + 255) / 256, 256, 0, s_side>>>(ei, e, n);
    scan1_kernel  <<<nblk, 1024, 0, s_side>>>(n);
    scan2_kernel  <<<1, 64, 0, s_side>>>(nblk);
    scan3sl_kernel<<<nblk, 1024, 0, s_side>>>(n);
    scatter_kernel<<<(e4 + 255) / 256, 256, 0, s_side>>>(ei, e, n);
    cudaEventRecord(ev_join, s_side);

    // main: prep || xconv, then GEMM1
    prep_kernel<<<(125952 + 255) / 256, 256>>>(
        Wl1, bl1, Wr1, br1, Ws, bs, Wl2, bl2, Wr2, br2,
        bias1, g1, b1, m1, v1, bias2, g2, b2, m2, v2);
    cudaStreamWaitEvent(0, ev_x, 0);
    {
        dim3 grid(576 / 64, (n + 127) / 128);
        gemm_mma_kernel<0><<<grid, 256, GEMM_SMEM>>>(n);
    }

    cudaStreamWaitEvent(0, ev_join, 0);

    conv1_agg_kernel<<<(n + 7) / 8, 256>>>(att1, n);
    {
        dim3 grid(128 / 64, (n + 127) / 128);
        gemm_mma_kernel<1><<<grid, 256, GEMM_SMEM>>>(n);
    }
    conv2_agg_kernel<<<(n + 7) / 8, 256>>>(att2, Wo, bo, (float*)d_out, n);
}